// round 14
// baseline (speedup 1.0000x reference)
#include <cuda_runtime.h>
#include <math.h>

static constexpr int T    = 300;
static constexpr int KSRM = 77;   // taps s = 0..76, SRM[0] == 0
static constexpr int KREF = 11;
static constexpr int JT   = 20;   // psp outputs per thread
static constexpr int NW   = 10;   // packed words per neuron

// ---------------- device-global scratch ----------------
__device__ float    g_SRM[KSRM];
__device__ float    g_REF[KREF];
__device__ float    g_bufY[39321600];
__device__ float    g_bufX[9830400];
__device__ float    g_bufZ[9830400];
__device__ unsigned g_bits[1310720];

__global__ void init_filters() {
    int i = threadIdx.x;
    if (i < KSRM) g_SRM[i] = (float)((double)i / 10.0 * exp(1.0 - (double)i / 10.0));
    if (i < KREF) g_REF[i] = (float)(-20.0 * (double)i * exp(1.0 - (double)i));
}

// ---------------- LUT builders ----------------
__device__ __forceinline__ void build_rlut(float* lut) {
    int nth = blockDim.x * blockDim.y;
    int tid = threadIdx.y * blockDim.x + threadIdx.x;
    for (int e = tid; e < 1024; e += nth) {
        float a = 0.f;
        #pragma unroll
        for (int i = 9; i >= 0; i--)
            if ((e >> i) & 1) a += g_REF[i + 1];
        lut[e] = a;
    }
}

__device__ __forceinline__ void build_slut(float* lut) {   // [10*256]
    int nth = blockDim.x * blockDim.y;
    int tid = threadIdx.y * blockDim.x + threadIdx.x;
    for (int e = tid; e < 2560; e += nth) {
        int j = e >> 8, b = e & 255;
        float a = 0.f;
        #pragma unroll
        for (int i = 0; i < 8; i++) {
            int s = 8 * j + i + 1;
            if (s < KSRM && ((b >> i) & 1)) a += g_SRM[s];
        }
        lut[e] = a;
    }
}

__device__ __forceinline__ float eval_psp(const float* slut,
                                          unsigned long long lo, unsigned int hi) {
    float y = 0.f;
    #pragma unroll
    for (int j = 0; j < 8; j++)
        y += slut[j * 256 + (int)((lo >> (8 * j)) & 0xFFull)];
    y += slut[8 * 256 + (int)(hi & 0xFFu)];
    y += slut[9 * 256 + (int)((hi >> 8) & 0xFFu)];
    return y;
}

struct BitWin { unsigned long long lo, stream; unsigned int hi; };

__device__ __forceinline__ BitWin load_win(const unsigned* __restrict__ bits,
                                           int M, int m, int t0) {
    int qlo = (t0 - 76) >> 5;
    unsigned wl[5];
    #pragma unroll
    for (int j = 0; j < 5; j++) {
        int q = qlo + j;
        wl[j] = (q >= 0 && q < NW) ? bits[(size_t)q * M + m] : 0u;
    }
    unsigned long long w01 = (unsigned long long)wl[0] | ((unsigned long long)wl[1] << 32);
    unsigned long long w23 = (unsigned long long)wl[2] | ((unsigned long long)wl[3] << 32);
    unsigned long long w45 = (unsigned long long)wl[4];
    int base = qlo << 5;
    int sh  = (t0 - 64) - base;
    int sh2 = (t0 - 76) - base;
    int sh3 = t0 - base;
    BitWin w;
    w.lo = __brevll((w01 >> sh) | (w23 << (64 - sh)));
    w.hi = __brev((unsigned)((w01 >> sh2) & 0xFFFull)) >> 20;
    w.stream = (w23 >> (sh3 - 64)) | (w45 << (128 - sh3));
    return w;
}

__device__ __forceinline__ void step_win(BitWin& w) {
    unsigned long long b = w.stream & 1ull;
    w.stream >>= 1;
    w.hi = ((w.hi << 1) | (unsigned int)(w.lo >> 63)) & 0xFFFu;
    w.lo = (w.lo << 1) | b;
}

// ---------------- pack binary input x (row-major (M,T)) into bit words ----------------
__global__ void pack_bits_rm(const float* __restrict__ x, unsigned* __restrict__ bits, int M) {
    int idx = blockIdx.x * blockDim.x + threadIdx.x;
    if (idx >= M * NW) return;
    int w = idx / M, m = idx % M;
    unsigned wd = 0;
    const float* p = x + (size_t)m * T + w * 32;
    #pragma unroll
    for (int i = 0; i < 32; i++) {
        int t = w * 32 + i;
        if (t < T) wd |= (p[i] != 0.f ? 1u : 0u) << i;
    }
    bits[(size_t)w * M + m] = wd;
}

// ---------------- FUSED: psp-from-count-bitplanes + spike scan -> packed spike bits ----------------
__global__ void spikecnt_bits(const unsigned* __restrict__ cnt, unsigned* __restrict__ bits,
                              int M) {
    __shared__ float rlut[1024];
    __shared__ float slut[2560];
    build_rlut(rlut);
    build_slut(slut);
    __syncthreads();
    int m = blockIdx.x * blockDim.x + threadIdx.x;
    if (m >= M) return;
    const unsigned* c0 = cnt + m;
    const unsigned* c1 = cnt + (size_t)NW * M + m;
    const unsigned* c2 = cnt + (size_t)2 * NW * M + m;
    unsigned long long lo0 = 0, lo1 = 0, lo2 = 0;
    unsigned hi0 = 0, hi1 = 0, hi2 = 0;
    unsigned rm = 0, word = 0;
    unsigned w0c = c0[0], w1c = c1[0], w2c = c2[0];
    unsigned w0n = 0, w1n = 0, w2n = 0;
    for (int t = 0; t < T; t++) {
        int sh = t & 31;
        if (sh == 0 && (t >> 5) + 1 < NW) {
            size_t q = (size_t)((t >> 5) + 1) * M;
            w0n = __ldg(&c0[q]); w1n = __ldg(&c1[q]); w2n = __ldg(&c2[q]);
        }
        float y0 = eval_psp(slut, lo0, hi0);
        float y1 = eval_psp(slut, lo1, hi1);
        float y2 = eval_psp(slut, lo2, hi2);
        float ueff = 2.75f * (y0 + 2.f * y1 + 4.f * y2) + rlut[rm];
        unsigned b = (ueff >= 10.f) ? 1u : 0u;
        rm = ((rm << 1) | b) & 1023u;
        word |= b << sh;
        if (sh == 31) { bits[(size_t)(t >> 5) * M + m] = word; word = 0; }
        unsigned b0 = (w0c >> sh) & 1u, b1 = (w1c >> sh) & 1u, b2 = (w2c >> sh) & 1u;
        hi0 = ((hi0 << 1) | (unsigned)(lo0 >> 63)) & 0xFFFu; lo0 = (lo0 << 1) | b0;
        hi1 = ((hi1 << 1) | (unsigned)(lo1 >> 63)) & 0xFFFu; lo1 = (lo1 << 1) | b1;
        hi2 = ((hi2 << 1) | (unsigned)(lo2 >> 63)) & 0xFFFu; lo2 = (lo2 << 1) | b2;
        if (sh == 31) { w0c = w0n; w1c = w1n; w2c = w2n; }
    }
    bits[(size_t)(NW - 1) * M + m] = word;
}

// ---------------- psp from packed binary spike bits, t-parallel ----------------
__global__ void psp_frombits(const unsigned* __restrict__ bits, float* __restrict__ out, int M) {
    __shared__ float slut[2560];
    build_slut(slut);
    __syncthreads();
    int m = blockIdx.x * blockDim.x + threadIdx.x;
    if (m >= M) return;
    int t0 = blockIdx.y * JT;
    BitWin w = load_win(bits, M, m, t0);
    float* po = out + (size_t)t0 * M + m;
    #pragma unroll
    for (int k = 0; k < JT; k++) {
        *po = eval_psp(slut, w.lo, w.hi);
        po += M;
        step_win(w);
    }
}

// ---------------- fused spike + 2x2 pool -> count bitplanes, prefetch depth 4 ----------------
template<int HI, int WI>
__global__ void spikepool_bits(const float* __restrict__ u, unsigned* __restrict__ cnt, int Mo) {
    __shared__ float lut[1024];
    build_rlut(lut);
    __syncthreads();
    int mo = blockIdx.x * blockDim.x + threadIdx.x;
    if (mo >= Mo) return;
    constexpr int WO = WI / 2, HO = HI / 2;
    int w = mo % WO; int r = mo / WO;
    int h = r % HO;  int nc = r / HO;
    int Mi = Mo * 4;
    const float* p = u + ((size_t)nc * HI + 2 * h) * WI + 2 * w;
    unsigned m0 = 0, m1 = 0, m2 = 0, m3 = 0;
    unsigned pw0 = 0, pw1 = 0, pw2 = 0;
    float cur[4][4], nxt[4][4];
    #pragma unroll
    for (int j = 0; j < 4; j++) {
        const float* pt = p + (size_t)j * Mi;
        cur[j][0] = pt[0]; cur[j][1] = pt[1]; cur[j][2] = pt[WI]; cur[j][3] = pt[WI + 1];
    }
    for (int tb = 0; tb < T; tb += 4) {
        if (tb + 4 < T) {
            #pragma unroll
            for (int j = 0; j < 4; j++) {
                const float* pt = p + (size_t)(tb + 4 + j) * Mi;
                nxt[j][0] = __ldg(&pt[0]);      nxt[j][1] = __ldg(&pt[1]);
                nxt[j][2] = __ldg(&pt[WI]);     nxt[j][3] = __ldg(&pt[WI + 1]);
            }
        }
        #pragma unroll
        for (int j = 0; j < 4; j++) {
            int t = tb + j;
            bool b0 = (cur[j][0] + lut[m0]) >= 10.f;
            bool b1 = (cur[j][1] + lut[m1]) >= 10.f;
            bool b2 = (cur[j][2] + lut[m2]) >= 10.f;
            bool b3 = (cur[j][3] + lut[m3]) >= 10.f;
            unsigned c = (unsigned)b0 + (unsigned)b1 + (unsigned)b2 + (unsigned)b3;
            int sh = t & 31;
            pw0 |= (c & 1u) << sh;
            pw1 |= ((c >> 1) & 1u) << sh;
            pw2 |= ((c >> 2) & 1u) << sh;
            if (sh == 31) {
                size_t q = (size_t)(t >> 5) * Mo + mo;
                cnt[q] = pw0;
                cnt[(size_t)NW * Mo + q] = pw1;
                cnt[(size_t)2 * NW * Mo + q] = pw2;
                pw0 = pw1 = pw2 = 0;
            }
            m0 = ((m0 << 1) | (unsigned)b0) & 1023u;
            m1 = ((m1 << 1) | (unsigned)b1) & 1023u;
            m2 = ((m2 << 1) | (unsigned)b2) & 1023u;
            m3 = ((m3 << 1) | (unsigned)b3) & 1023u;
        }
        #pragma unroll
        for (int j = 0; j < 4; j++)
            #pragma unroll
            for (int v = 0; v < 4; v++) cur[j][v] = nxt[j][v];
    }
    size_t q = (size_t)(NW - 1) * Mo + mo;
    cnt[q] = pw0;
    cnt[(size_t)NW * Mo + q] = pw1;
    cnt[(size_t)2 * NW * Mo + q] = pw2;
}

// ---------------- spike scan -> FLOAT spikes (t-major), prefetch depth 4 ----------------
__global__ void spike_f(const float* __restrict__ u, float* __restrict__ s, int M) {
    __shared__ float rlut[1024];
    build_rlut(rlut);
    __syncthreads();
    int m = blockIdx.x * blockDim.x + threadIdx.x;
    if (m >= M) return;
    unsigned rm = 0;
    float cur[4], nxt[4];
    #pragma unroll
    for (int j = 0; j < 4; j++) cur[j] = u[(size_t)j * M + m];
    for (int tb = 0; tb < T; tb += 4) {
        if (tb + 4 < T) {
            #pragma unroll
            for (int j = 0; j < 4; j++) nxt[j] = __ldg(&u[(size_t)(tb + 4 + j) * M + m]);
        }
        #pragma unroll
        for (int j = 0; j < 4; j++) {
            float ueff = cur[j] + rlut[rm];
            unsigned b = (ueff >= 10.f) ? 1u : 0u;
            rm = ((rm << 1) | b) & 1023u;
            s[(size_t)(tb + j) * M + m] = b ? 1.f : 0.f;
        }
        #pragma unroll
        for (int j = 0; j < 4; j++) cur[j] = nxt[j];
    }
}

// ---------------- dense psp FIR (tiny, 80 rows), JT=20 ----------------
template<bool INTERIOR>
__device__ __forceinline__ void psp_body(const float* __restrict__ in,
                                         float* __restrict__ out,
                                         const float* ssrm, int M, int m, int t0) {
    float acc[JT];
    float xv[JT];
    #pragma unroll
    for (int j = 0; j < JT; j++) acc[j] = 0.f;
    {
        const float* p = in + m + (size_t)(t0 - 1) * M;
        #pragma unroll
        for (int j = 0; j < JT; j++) {
            int slot = ((j - 1) % JT + JT) % JT;
            xv[slot] = (INTERIOR || (t0 + j - 1) >= 0) ? __ldg(p) : 0.f;
            p += M;
        }
    }
    const float* pd = in + m + (size_t)(t0 - 2) * M;
    #pragma unroll
    for (int s = 1; s < KSRM; s++) {
        float wt = ssrm[s];
        #pragma unroll
        for (int j = 0; j < JT; j++) {
            int slot = (((j - s) % JT) + JT) % JT;
            acc[j] = fmaf(wt, xv[slot], acc[j]);
        }
        if (s < KSRM - 1) {
            int slot = (((-s - 1) % JT) + JT) % JT;
            xv[slot] = (INTERIOR || (t0 - s - 1) >= 0) ? __ldg(pd) : 0.f;
            pd -= M;
        }
    }
    float* po = out + (size_t)t0 * M + m;
    #pragma unroll
    for (int j = 0; j < JT; j++) { *po = acc[j]; po += M; }
}

__global__ void psp_t(const float* __restrict__ in, float* __restrict__ out, int M) {
    __shared__ float ssrm[KSRM];
    for (int i = threadIdx.x; i < KSRM; i += blockDim.x) ssrm[i] = g_SRM[i];
    __syncthreads();
    int m = blockIdx.x * blockDim.x + threadIdx.x;
    if (m >= M) return;
    int t0 = blockIdx.y * JT;
    if (t0 >= KSRM + JT) psp_body<true >(in, out, ssrm, M, m, t0);
    else                 psp_body<false>(in, out, ssrm, M, m, t0);
}

// ---------------- double-buffered conv: loops NT timesteps, LDG hidden ----------------
template<int CIN, int K, int HIN, int WIN, int HOUT, int WOUT,
         int COUT, int OBLK, int OV, int WV, int NT, int THR>
__global__ void conv_db(const float* __restrict__ in, const float* __restrict__ wgt,
                        float* __restrict__ out, int Min, int Mout) {
    constexpr int HP   = HIN + 2;
    constexpr int WPAD = (WIN + 2 + 3) & ~3;
    constexpr int KP   = (K + 3) & ~3;
    constexpr int TILE = CIN * HP * WPAD;
    constexpr int CHW  = CIN * HIN * WIN;
    constexpr int WLEN = WV + K - 1;
    constexpr int WTHR = WOUT / WV;
    constexpr int CKK  = CIN * K * K;
    constexpr int NSTG = (CHW + THR - 1) / THR;
    extern __shared__ float smem[];
    float* s_in = smem;
    float* s_w  = smem + 2 * TILE;

    int t0 = blockIdx.z * NT, n = blockIdx.y, o0 = blockIdx.x * OBLK;
    int tid = threadIdx.y * blockDim.x + threadIdx.x;

    for (int i = tid; i < 2 * TILE; i += THR) s_in[i] = 0.f;
    for (int i = tid; i < OBLK * CKK; i += THR) {
        int o = i / CKK, r = i % CKK;
        s_w[(o * CIN * K + r / K) * KP + r % K] = wgt[(size_t)(o0 + o) * CKK + r];
    }
    __syncthreads();
    {
        const float* inb = in + (size_t)t0 * Min + (size_t)n * CHW;
        for (int i = tid; i < CHW; i += THR) {
            int c = i / (HIN * WIN), r = i % (HIN * WIN);
            s_in[(c * HP + r / WIN + 1) * WPAD + r % WIN + 1] = inb[i];
        }
    }
    __syncthreads();

    int w0 = (threadIdx.x % WTHR) * WV;
    int h  = threadIdx.x / WTHR;
    int oo = threadIdx.y * OV;
    int p  = 0;

    for (int k = 0; k < NT; k++) {
        int t = t0 + k;
        float stg[NSTG];
        if (k + 1 < NT) {
            const float* nb = in + (size_t)(t + 1) * Min + (size_t)n * CHW;
            #pragma unroll
            for (int j = 0; j < NSTG; j++) {
                int idx = tid + j * THR;
                stg[j] = (idx < CHW) ? __ldg(&nb[idx]) : 0.f;
            }
        }
        const float* sb = s_in + p * TILE;
        float acc[OV][WV];
        #pragma unroll
        for (int o = 0; o < OV; o++)
            #pragma unroll
            for (int v = 0; v < WV; v++) acc[o][v] = 0.f;

        #pragma unroll 2
        for (int c = 0; c < CIN; c++) {
            #pragma unroll
            for (int kh = 0; kh < K; kh++) {
                float win[WLEN];
                const float* bp = &sb[(c * HP + h + kh) * WPAD + w0];
                if constexpr (WLEN == 8) {
                    float4 a = *reinterpret_cast<const float4*>(bp);
                    float4 b = *reinterpret_cast<const float4*>(bp + 4);
                    win[0] = a.x; win[1] = a.y; win[2] = a.z; win[3] = a.w;
                    win[4] = b.x; win[5] = b.y; win[6] = b.z; win[7] = b.w;
                } else {
                    float4 a = *reinterpret_cast<const float4*>(bp);
                    float2 b = *reinterpret_cast<const float2*>(bp + 4);
                    win[0] = a.x; win[1] = a.y; win[2] = a.z; win[3] = a.w;
                    win[4] = b.x; win[5] = b.y;
                }
                #pragma unroll
                for (int o = 0; o < OV; o++) {
                    const float* wp = &s_w[((oo + o) * CIN * K + c * K + kh) * KP];
                    float wr[K];
                    if constexpr (K == 5) {
                        float4 a = *reinterpret_cast<const float4*>(wp);
                        wr[0] = a.x; wr[1] = a.y; wr[2] = a.z; wr[3] = a.w; wr[4] = wp[4];
                    } else {
                        float4 a = *reinterpret_cast<const float4*>(wp);
                        wr[0] = a.x; wr[1] = a.y; wr[2] = a.z;
                    }
                    #pragma unroll
                    for (int kw = 0; kw < K; kw++)
                        #pragma unroll
                        for (int v = 0; v < WV; v++)
                            acc[o][v] = fmaf(wr[kw], win[kw + v], acc[o][v]);
                }
            }
        }
        size_t ob = (size_t)t * Mout + (((size_t)n * COUT + o0 + oo) * HOUT + h) * WOUT + w0;
        #pragma unroll
        for (int o = 0; o < OV; o++)
            #pragma unroll
            for (int v = 0; v < WV; v++)
                out[ob + (size_t)o * (HOUT * WOUT) + v] = acc[o][v];

        if (k + 1 < NT) {
            float* db = s_in + (p ^ 1) * TILE;
            #pragma unroll
            for (int j = 0; j < NSTG; j++) {
                int idx = tid + j * THR;
                if (idx < CHW) {
                    int c = idx / (HIN * WIN), r = idx % (HIN * WIN);
                    db[(c * HP + r / WIN + 1) * WPAD + r % WIN + 1] = stg[j];
                }
            }
        }
        __syncthreads();
        p ^= 1;
    }
}

// ---------------- static conv (conv3): TT timesteps per block ----------------
template<int CIN, int K, int HIN, int WIN, int HOUT, int WOUT,
         int COUT, int OBLK, int OV, int WV, int TT>
__global__ void conv_p(const float* __restrict__ in, const float* __restrict__ wgt,
                       float* __restrict__ out, int Min, int Mout) {
    constexpr int HP    = HIN + 2;
    constexpr int WPAD  = (WIN + 2 + 3) & ~3;
    constexpr int KP    = (K + 3) & ~3;
    constexpr int TILE  = CIN * HP * WPAD;
    constexpr int WLEN  = WV + K - 1;
    constexpr int WTHR  = WOUT / WV;
    constexpr int CKK   = CIN * K * K;
    extern __shared__ float smem[];
    float* s_in = smem;
    float* s_w  = smem + TT * TILE;

    int t0 = blockIdx.z * TT, n = blockIdx.y, o0 = blockIdx.x * OBLK;
    int nth = blockDim.x * blockDim.y;
    int tid = threadIdx.y * blockDim.x + threadIdx.x;

    for (int i = tid; i < TT * TILE; i += nth) s_in[i] = 0.f;
    __syncthreads();
    #pragma unroll
    for (int tt = 0; tt < TT; tt++) {
        const float* inb = in + (size_t)(t0 + tt) * Min + (size_t)n * CIN * HIN * WIN;
        for (int i = tid; i < CIN * HIN * WIN; i += nth) {
            int c = i / (HIN * WIN), r = i % (HIN * WIN);
            s_in[tt * TILE + (c * HP + r / WIN + 1) * WPAD + r % WIN + 1] = inb[i];
        }
    }
    for (int i = tid; i < OBLK * CKK; i += nth) {
        int o = i / CKK, r = i % CKK;
        s_w[(o * CIN * K + r / K) * KP + r % K] = wgt[(size_t)(o0 + o) * CKK + r];
    }
    __syncthreads();

    int w0 = (threadIdx.x % WTHR) * WV;
    int h  = threadIdx.x / WTHR;
    int oo = threadIdx.y * OV;

    float acc[TT][OV][WV];
    #pragma unroll
    for (int tt = 0; tt < TT; tt++)
        #pragma unroll
        for (int o = 0; o < OV; o++)
            #pragma unroll
            for (int v = 0; v < WV; v++) acc[tt][o][v] = 0.f;

    #pragma unroll 2
    for (int c = 0; c < CIN; c++) {
        #pragma unroll
        for (int kh = 0; kh < K; kh++) {
            float win[TT][WLEN];
            #pragma unroll
            for (int tt = 0; tt < TT; tt++) {
                const float* bp = &s_in[tt * TILE + (c * HP + h + kh) * WPAD + w0];
                float4 a = *reinterpret_cast<const float4*>(bp);
                float2 b = *reinterpret_cast<const float2*>(bp + 4);
                win[tt][0] = a.x; win[tt][1] = a.y; win[tt][2] = a.z; win[tt][3] = a.w;
                win[tt][4] = b.x; win[tt][5] = b.y;
            }
            #pragma unroll
            for (int o = 0; o < OV; o++) {
                const float* wp = &s_w[((oo + o) * CIN * K + c * K + kh) * KP];
                float4 a = *reinterpret_cast<const float4*>(wp);
                float wr[3] = {a.x, a.y, a.z};
                #pragma unroll
                for (int kw = 0; kw < K; kw++)
                    #pragma unroll
                    for (int tt = 0; tt < TT; tt++)
                        #pragma unroll
                        for (int v = 0; v < WV; v++)
                            acc[tt][o][v] = fmaf(wr[kw], win[tt][kw + v], acc[tt][o][v]);
            }
        }
    }
    #pragma unroll
    for (int tt = 0; tt < TT; tt++) {
        size_t ob = (size_t)(t0 + tt) * Mout
                  + (((size_t)n * COUT + o0 + oo) * HOUT + h) * WOUT + w0;
        #pragma unroll
        for (int o = 0; o < OV; o++)
            #pragma unroll
            for (int v = 0; v < WV; v++)
                out[ob + (size_t)o * (HOUT * WOUT) + v] = acc[tt][o][v];
    }
}

// ---------------- final spike scan -> T-minor d_out ----------------
__global__ void spike_lut_out(const float* __restrict__ u, float* __restrict__ out, int M) {
    __shared__ float lut[1024];
    build_rlut(lut);
    __syncthreads();
    int m = blockIdx.x * blockDim.x + threadIdx.x;
    if (m >= M) return;
    unsigned mask = 0;
    float cur[4], nxt[4];
    #pragma unroll
    for (int j = 0; j < 4; j++) cur[j] = u[(size_t)j * M + m];
    for (int tb = 0; tb < T; tb += 4) {
        if (tb + 4 < T) {
            #pragma unroll
            for (int j = 0; j < 4; j++) nxt[j] = __ldg(&u[(size_t)(tb + 4 + j) * M + m]);
        }
        #pragma unroll
        for (int j = 0; j < 4; j++) {
            int t = tb + j;
            float ueff = cur[j] + lut[mask];
            bool b = ueff >= 10.f;
            out[(size_t)m * T + t] = b ? 1.f : 0.f;
            mask = ((mask << 1) | (unsigned)b) & 1023u;
        }
        #pragma unroll
        for (int j = 0; j < 4; j++) cur[j] = nxt[j];
    }
}

// ---------------- dense on s5: double-buffered smem, warp per output ----------------
__global__ void dense_w(const float* __restrict__ in, const float* __restrict__ wfc,
                        float* __restrict__ out) {
    __shared__ float s_in[2][4096];
    int n = blockIdx.x, tg = blockIdx.y;
    int tid = threadIdx.x;                 // 320
    int o = tid >> 5, lane = tid & 31;
    const float* pw = wfc + o * 4096;
    {
        const float* pin = in + (size_t)(tg * 10) * 32768 + n * 4096;
        for (int i = tid; i < 4096; i += 320) s_in[0][i] = pin[i];
    }
    __syncthreads();
    for (int k = 0; k < 10; k++) {
        int t = tg * 10 + k;
        if (k + 1 < 10) {
            const float* pin = in + (size_t)(t + 1) * 32768 + n * 4096;
            for (int i = tid; i < 4096; i += 320) s_in[(k + 1) & 1][i] = __ldg(&pin[i]);
        }
        const float* sb = s_in[k & 1];
        float acc = 0.f;
        #pragma unroll 4
        for (int i = lane; i < 4096; i += 32) acc = fmaf(pw[i], sb[i], acc);
        #pragma unroll
        for (int off = 16; off; off >>= 1) acc += __shfl_down_sync(0xffffffffu, acc, off);
        if (lane == 0) out[(size_t)t * 80 + n * 10 + o] = acc;
        __syncthreads();
    }
}

// ---------------- launch ----------------
extern "C" void kernel_launch(void* const* d_in, const int* in_sizes, int n_in,
                              void* d_out, int out_size) {
    const float* x   = (const float*)d_in[0];
    const float* w1  = (const float*)d_in[1];
    const float* w2  = (const float*)d_in[2];
    const float* w3  = (const float*)d_in[3];
    const float* wfc = (const float*)d_in[4];
    float* out = (float*)d_out;

    void *pY, *pX, *pZ, *pB;
    cudaGetSymbolAddress(&pY, g_bufY);
    cudaGetSymbolAddress(&pX, g_bufX);
    cudaGetSymbolAddress(&pZ, g_bufZ);
    cudaGetSymbolAddress(&pB, g_bits);
    float* Y = (float*)pY;
    float* X = (float*)pX;
    float* Z = (float*)pZ;
    unsigned* B  = (unsigned*)pB;
    unsigned* CB = B + 327680;

    auto c1 = conv_db<2, 5, 34, 34, 32, 32, 16, 4, 4, 4, 5, 256>;
    auto c2 = conv_db<16, 3, 16, 16, 16, 16, 32, 32, 4, 4, 6, 512>;
    auto c3 = conv_p<32, 3, 8, 8, 8, 8, 64, 32, 2, 4, 4>;
    const int s1b = (2 * 2 * 36 * 36 + 4 * 2 * 5 * 8) * 4;          // ~22 KB
    const int s2b = (2 * 16 * 18 * 20 + 32 * 16 * 3 * 4) * 4;       // ~70.7 KB (db: 2 tiles + wgt)
    const int s3b = (4 * 32 * 10 * 12 + 32 * 32 * 3 * 4) * 4;       // ~110.6 KB
    cudaFuncSetAttribute(c2, cudaFuncAttributeMaxDynamicSharedMemorySize, s2b);
    cudaFuncSetAttribute(c3, cudaFuncAttributeMaxDynamicSharedMemorySize, s3b);

    init_filters<<<1, 128>>>();

    // ---- layer 1: psp(x) -> conv1 -> spikepool (count bitplanes) ----
    pack_bits_rm<<<(18496 * NW + 255) / 256, 256>>>(x, B, 18496);
    psp_frombits<<<dim3(73, T / JT), 256>>>(B, X, 18496);
    c1<<<dim3(4, 8, T / 5), dim3(256, 1), s1b>>>(X, w1, Y, 18496, 131072);
    spikepool_bits<32, 32><<<128, 256>>>(Y, CB, 32768);

    // ---- layer 2 tail + layer 3 (conv2 now pipelined, 400-block single wave) ----
    spikecnt_bits<<<128, 256>>>(CB, B, 32768);
    psp_frombits<<<dim3(128, T / JT), 256>>>(B, X, 32768);
    c2<<<dim3(1, 8, T / 6), dim3(64, 8), s2b>>>(X, w2, Y, 32768, 65536);
    spikepool_bits<16, 16><<<64, 256>>>(Y, CB, 16384);

    // ---- layer 4 tail + layer 5 ----
    spikecnt_bits<<<64, 256>>>(CB, B, 16384);
    psp_frombits<<<dim3(64, T / JT), 256>>>(B, X, 16384);
    c3<<<dim3(2, 8, T / 4), dim3(16, 16), s3b>>>(X, w3, Y, 16384, 32768);

    // ---- output (commuted): s5 float -> dense(s5) -> psp (tiny) -> spike ----
    spike_f<<<128, 256>>>(Y, X, 32768);
    dense_w<<<dim3(8, T / 10), 320>>>(X, wfc, Z);
    psp_t<<<dim3(1, T / JT), 256>>>(Z, Z + 1048576, 80);
    spike_lut_out<<<1, 128>>>(Z + 1048576, out, 80);
}

// round 15
// speedup vs baseline: 1.0527x; 1.0527x over previous
#include <cuda_runtime.h>
#include <math.h>

static constexpr int T    = 300;
static constexpr int KSRM = 77;   // taps s = 0..76, SRM[0] == 0
static constexpr int KREF = 11;
static constexpr int JT   = 20;   // psp outputs per thread
static constexpr int NW   = 10;   // packed words per neuron

// ---------------- device-global scratch ----------------
__device__ float    g_SRM[KSRM];
__device__ float    g_REF[KREF];
__device__ float    g_bufY[39321600];
__device__ float    g_bufX[9830400];
__device__ float    g_bufZ[9830400];
__device__ unsigned g_bits[1310720];

__global__ void init_filters() {
    int i = threadIdx.x;
    if (i < KSRM) g_SRM[i] = (float)((double)i / 10.0 * exp(1.0 - (double)i / 10.0));
    if (i < KREF) g_REF[i] = (float)(-20.0 * (double)i * exp(1.0 - (double)i));
}

// ---------------- LUT builders ----------------
__device__ __forceinline__ void build_rlut(float* lut) {
    int nth = blockDim.x * blockDim.y;
    int tid = threadIdx.y * blockDim.x + threadIdx.x;
    for (int e = tid; e < 1024; e += nth) {
        float a = 0.f;
        #pragma unroll
        for (int i = 9; i >= 0; i--)
            if ((e >> i) & 1) a += g_REF[i + 1];
        lut[e] = a;
    }
}

__device__ __forceinline__ void build_slut(float* lut) {   // [10*256]
    int nth = blockDim.x * blockDim.y;
    int tid = threadIdx.y * blockDim.x + threadIdx.x;
    for (int e = tid; e < 2560; e += nth) {
        int j = e >> 8, b = e & 255;
        float a = 0.f;
        #pragma unroll
        for (int i = 0; i < 8; i++) {
            int s = 8 * j + i + 1;
            if (s < KSRM && ((b >> i) & 1)) a += g_SRM[s];
        }
        lut[e] = a;
    }
}

__device__ __forceinline__ float eval_psp(const float* slut,
                                          unsigned long long lo, unsigned int hi) {
    float y = 0.f;
    #pragma unroll
    for (int j = 0; j < 8; j++)
        y += slut[j * 256 + (int)((lo >> (8 * j)) & 0xFFull)];
    y += slut[8 * 256 + (int)(hi & 0xFFu)];
    y += slut[9 * 256 + (int)((hi >> 8) & 0xFFu)];
    return y;
}

struct BitWin { unsigned long long lo, stream; unsigned int hi; };

__device__ __forceinline__ BitWin load_win(const unsigned* __restrict__ bits,
                                           int M, int m, int t0) {
    int qlo = (t0 - 76) >> 5;
    unsigned wl[5];
    #pragma unroll
    for (int j = 0; j < 5; j++) {
        int q = qlo + j;
        wl[j] = (q >= 0 && q < NW) ? bits[(size_t)q * M + m] : 0u;
    }
    unsigned long long w01 = (unsigned long long)wl[0] | ((unsigned long long)wl[1] << 32);
    unsigned long long w23 = (unsigned long long)wl[2] | ((unsigned long long)wl[3] << 32);
    unsigned long long w45 = (unsigned long long)wl[4];
    int base = qlo << 5;
    int sh  = (t0 - 64) - base;
    int sh2 = (t0 - 76) - base;
    int sh3 = t0 - base;
    BitWin w;
    w.lo = __brevll((w01 >> sh) | (w23 << (64 - sh)));
    w.hi = __brev((unsigned)((w01 >> sh2) & 0xFFFull)) >> 20;
    w.stream = (w23 >> (sh3 - 64)) | (w45 << (128 - sh3));
    return w;
}

__device__ __forceinline__ void step_win(BitWin& w) {
    unsigned long long b = w.stream & 1ull;
    w.stream >>= 1;
    w.hi = ((w.hi << 1) | (unsigned int)(w.lo >> 63)) & 0xFFFu;
    w.lo = (w.lo << 1) | b;
}

// ---------------- pack binary input x (row-major (M,T)) into bit words ----------------
__global__ void pack_bits_rm(const float* __restrict__ x, unsigned* __restrict__ bits, int M) {
    int idx = blockIdx.x * blockDim.x + threadIdx.x;
    if (idx >= M * NW) return;
    int w = idx / M, m = idx % M;
    unsigned wd = 0;
    const float* p = x + (size_t)m * T + w * 32;
    #pragma unroll
    for (int i = 0; i < 32; i++) {
        int t = w * 32 + i;
        if (t < T) wd |= (p[i] != 0.f ? 1u : 0u) << i;
    }
    bits[(size_t)w * M + m] = wd;
}

// ---------------- FUSED: psp-from-count-bitplanes + spike scan -> packed spike bits ----------------
// Warp-uniform zero-window skip: a plane whose 76-bit history is zero contributes
// exactly 0.0 (all slut[*][0] entries are 0.0), so the skip is bit-exact.
__global__ void spikecnt_bits(const unsigned* __restrict__ cnt, unsigned* __restrict__ bits,
                              int M) {
    __shared__ float rlut[1024];
    __shared__ float slut[2560];
    build_rlut(rlut);
    build_slut(slut);
    __syncthreads();
    int m = blockIdx.x * blockDim.x + threadIdx.x;
    if (m >= M) return;
    unsigned amask = __activemask();
    const unsigned* c0 = cnt + m;
    const unsigned* c1 = cnt + (size_t)NW * M + m;
    const unsigned* c2 = cnt + (size_t)2 * NW * M + m;
    unsigned long long lo0 = 0, lo1 = 0, lo2 = 0;
    unsigned hi0 = 0, hi1 = 0, hi2 = 0;
    unsigned rm = 0, word = 0;
    unsigned w0c = c0[0], w1c = c1[0], w2c = c2[0];
    unsigned w0n = 0, w1n = 0, w2n = 0;
    for (int t = 0; t < T; t++) {
        int sh = t & 31;
        if (sh == 0 && (t >> 5) + 1 < NW) {
            size_t q = (size_t)((t >> 5) + 1) * M;
            w0n = __ldg(&c0[q]); w1n = __ldg(&c1[q]); w2n = __ldg(&c2[q]);
        }
        float y0 = 0.f, y1 = 0.f, y2 = 0.f;
        if (!__all_sync(amask, (lo0 | (unsigned long long)hi0) == 0ull))
            y0 = eval_psp(slut, lo0, hi0);
        if (!__all_sync(amask, (lo1 | (unsigned long long)hi1) == 0ull))
            y1 = eval_psp(slut, lo1, hi1);
        if (!__all_sync(amask, (lo2 | (unsigned long long)hi2) == 0ull))
            y2 = eval_psp(slut, lo2, hi2);
        float ueff = 2.75f * (y0 + 2.f * y1 + 4.f * y2) + rlut[rm];
        unsigned b = (ueff >= 10.f) ? 1u : 0u;
        rm = ((rm << 1) | b) & 1023u;
        word |= b << sh;
        if (sh == 31) { bits[(size_t)(t >> 5) * M + m] = word; word = 0; }
        unsigned b0 = (w0c >> sh) & 1u, b1 = (w1c >> sh) & 1u, b2 = (w2c >> sh) & 1u;
        hi0 = ((hi0 << 1) | (unsigned)(lo0 >> 63)) & 0xFFFu; lo0 = (lo0 << 1) | b0;
        hi1 = ((hi1 << 1) | (unsigned)(lo1 >> 63)) & 0xFFFu; lo1 = (lo1 << 1) | b1;
        hi2 = ((hi2 << 1) | (unsigned)(lo2 >> 63)) & 0xFFFu; lo2 = (lo2 << 1) | b2;
        if (sh == 31) { w0c = w0n; w1c = w1n; w2c = w2n; }
    }
    bits[(size_t)(NW - 1) * M + m] = word;
}

// ---------------- psp from packed binary spike bits, t-parallel ----------------
__global__ void psp_frombits(const unsigned* __restrict__ bits, float* __restrict__ out, int M) {
    __shared__ float slut[2560];
    build_slut(slut);
    __syncthreads();
    int m = blockIdx.x * blockDim.x + threadIdx.x;
    if (m >= M) return;
    unsigned amask = __activemask();
    int t0 = blockIdx.y * JT;
    BitWin w = load_win(bits, M, m, t0);
    float* po = out + (size_t)t0 * M + m;
    // whole-tile zero fast path (exact: empty-byte LUT entries are 0.0)
    if (__all_sync(amask, (w.lo | w.stream | (unsigned long long)w.hi) == 0ull)) {
        #pragma unroll
        for (int k = 0; k < JT; k++) { *po = 0.f; po += M; }
        return;
    }
    #pragma unroll
    for (int k = 0; k < JT; k++) {
        *po = eval_psp(slut, w.lo, w.hi);
        po += M;
        step_win(w);
    }
}

// ---------------- fused spike + 2x2 pool -> count bitplanes, prefetch depth 4 ----------------
template<int HI, int WI>
__global__ void spikepool_bits(const float* __restrict__ u, unsigned* __restrict__ cnt, int Mo) {
    __shared__ float lut[1024];
    build_rlut(lut);
    __syncthreads();
    int mo = blockIdx.x * blockDim.x + threadIdx.x;
    if (mo >= Mo) return;
    constexpr int WO = WI / 2, HO = HI / 2;
    int w = mo % WO; int r = mo / WO;
    int h = r % HO;  int nc = r / HO;
    int Mi = Mo * 4;
    const float* p = u + ((size_t)nc * HI + 2 * h) * WI + 2 * w;
    unsigned m0 = 0, m1 = 0, m2 = 0, m3 = 0;
    unsigned pw0 = 0, pw1 = 0, pw2 = 0;
    float cur[4][4], nxt[4][4];
    #pragma unroll
    for (int j = 0; j < 4; j++) {
        const float* pt = p + (size_t)j * Mi;
        cur[j][0] = pt[0]; cur[j][1] = pt[1]; cur[j][2] = pt[WI]; cur[j][3] = pt[WI + 1];
    }
    for (int tb = 0; tb < T; tb += 4) {
        if (tb + 4 < T) {
            #pragma unroll
            for (int j = 0; j < 4; j++) {
                const float* pt = p + (size_t)(tb + 4 + j) * Mi;
                nxt[j][0] = __ldg(&pt[0]);      nxt[j][1] = __ldg(&pt[1]);
                nxt[j][2] = __ldg(&pt[WI]);     nxt[j][3] = __ldg(&pt[WI + 1]);
            }
        }
        #pragma unroll
        for (int j = 0; j < 4; j++) {
            int t = tb + j;
            bool b0 = (cur[j][0] + lut[m0]) >= 10.f;
            bool b1 = (cur[j][1] + lut[m1]) >= 10.f;
            bool b2 = (cur[j][2] + lut[m2]) >= 10.f;
            bool b3 = (cur[j][3] + lut[m3]) >= 10.f;
            unsigned c = (unsigned)b0 + (unsigned)b1 + (unsigned)b2 + (unsigned)b3;
            int sh = t & 31;
            pw0 |= (c & 1u) << sh;
            pw1 |= ((c >> 1) & 1u) << sh;
            pw2 |= ((c >> 2) & 1u) << sh;
            if (sh == 31) {
                size_t q = (size_t)(t >> 5) * Mo + mo;
                cnt[q] = pw0;
                cnt[(size_t)NW * Mo + q] = pw1;
                cnt[(size_t)2 * NW * Mo + q] = pw2;
                pw0 = pw1 = pw2 = 0;
            }
            m0 = ((m0 << 1) | (unsigned)b0) & 1023u;
            m1 = ((m1 << 1) | (unsigned)b1) & 1023u;
            m2 = ((m2 << 1) | (unsigned)b2) & 1023u;
            m3 = ((m3 << 1) | (unsigned)b3) & 1023u;
        }
        #pragma unroll
        for (int j = 0; j < 4; j++)
            #pragma unroll
            for (int v = 0; v < 4; v++) cur[j][v] = nxt[j][v];
    }
    size_t q = (size_t)(NW - 1) * Mo + mo;
    cnt[q] = pw0;
    cnt[(size_t)NW * Mo + q] = pw1;
    cnt[(size_t)2 * NW * Mo + q] = pw2;
}

// ---------------- spike scan -> FLOAT spikes (t-major), prefetch depth 4 ----------------
__global__ void spike_f(const float* __restrict__ u, float* __restrict__ s, int M) {
    __shared__ float rlut[1024];
    build_rlut(rlut);
    __syncthreads();
    int m = blockIdx.x * blockDim.x + threadIdx.x;
    if (m >= M) return;
    unsigned rm = 0;
    float cur[4], nxt[4];
    #pragma unroll
    for (int j = 0; j < 4; j++) cur[j] = u[(size_t)j * M + m];
    for (int tb = 0; tb < T; tb += 4) {
        if (tb + 4 < T) {
            #pragma unroll
            for (int j = 0; j < 4; j++) nxt[j] = __ldg(&u[(size_t)(tb + 4 + j) * M + m]);
        }
        #pragma unroll
        for (int j = 0; j < 4; j++) {
            float ueff = cur[j] + rlut[rm];
            unsigned b = (ueff >= 10.f) ? 1u : 0u;
            rm = ((rm << 1) | b) & 1023u;
            s[(size_t)(tb + j) * M + m] = b ? 1.f : 0.f;
        }
        #pragma unroll
        for (int j = 0; j < 4; j++) cur[j] = nxt[j];
    }
}

// ---------------- dense psp FIR (tiny, 80 rows), JT=20 ----------------
template<bool INTERIOR>
__device__ __forceinline__ void psp_body(const float* __restrict__ in,
                                         float* __restrict__ out,
                                         const float* ssrm, int M, int m, int t0) {
    float acc[JT];
    float xv[JT];
    #pragma unroll
    for (int j = 0; j < JT; j++) acc[j] = 0.f;
    {
        const float* p = in + m + (size_t)(t0 - 1) * M;
        #pragma unroll
        for (int j = 0; j < JT; j++) {
            int slot = ((j - 1) % JT + JT) % JT;
            xv[slot] = (INTERIOR || (t0 + j - 1) >= 0) ? __ldg(p) : 0.f;
            p += M;
        }
    }
    const float* pd = in + m + (size_t)(t0 - 2) * M;
    #pragma unroll
    for (int s = 1; s < KSRM; s++) {
        float wt = ssrm[s];
        #pragma unroll
        for (int j = 0; j < JT; j++) {
            int slot = (((j - s) % JT) + JT) % JT;
            acc[j] = fmaf(wt, xv[slot], acc[j]);
        }
        if (s < KSRM - 1) {
            int slot = (((-s - 1) % JT) + JT) % JT;
            xv[slot] = (INTERIOR || (t0 - s - 1) >= 0) ? __ldg(pd) : 0.f;
            pd -= M;
        }
    }
    float* po = out + (size_t)t0 * M + m;
    #pragma unroll
    for (int j = 0; j < JT; j++) { *po = acc[j]; po += M; }
}

__global__ void psp_t(const float* __restrict__ in, float* __restrict__ out, int M) {
    __shared__ float ssrm[KSRM];
    for (int i = threadIdx.x; i < KSRM; i += blockDim.x) ssrm[i] = g_SRM[i];
    __syncthreads();
    int m = blockIdx.x * blockDim.x + threadIdx.x;
    if (m >= M) return;
    int t0 = blockIdx.y * JT;
    if (t0 >= KSRM + JT) psp_body<true >(in, out, ssrm, M, m, t0);
    else                 psp_body<false>(in, out, ssrm, M, m, t0);
}

// ---------------- double-buffered conv (conv1): loops NT timesteps, LDG hidden ----------------
template<int CIN, int K, int HIN, int WIN, int HOUT, int WOUT,
         int COUT, int OBLK, int OV, int WV, int NT, int THR>
__global__ void conv_db(const float* __restrict__ in, const float* __restrict__ wgt,
                        float* __restrict__ out, int Min, int Mout) {
    constexpr int HP   = HIN + 2;
    constexpr int WPAD = (WIN + 2 + 3) & ~3;
    constexpr int KP   = (K + 3) & ~3;
    constexpr int TILE = CIN * HP * WPAD;
    constexpr int CHW  = CIN * HIN * WIN;
    constexpr int WLEN = WV + K - 1;
    constexpr int WTHR = WOUT / WV;
    constexpr int CKK  = CIN * K * K;
    constexpr int NSTG = (CHW + THR - 1) / THR;
    extern __shared__ float smem[];
    float* s_in = smem;
    float* s_w  = smem + 2 * TILE;

    int t0 = blockIdx.z * NT, n = blockIdx.y, o0 = blockIdx.x * OBLK;
    int tid = threadIdx.y * blockDim.x + threadIdx.x;

    for (int i = tid; i < 2 * TILE; i += THR) s_in[i] = 0.f;
    for (int i = tid; i < OBLK * CKK; i += THR) {
        int o = i / CKK, r = i % CKK;
        s_w[(o * CIN * K + r / K) * KP + r % K] = wgt[(size_t)(o0 + o) * CKK + r];
    }
    __syncthreads();
    {
        const float* inb = in + (size_t)t0 * Min + (size_t)n * CHW;
        for (int i = tid; i < CHW; i += THR) {
            int c = i / (HIN * WIN), r = i % (HIN * WIN);
            s_in[(c * HP + r / WIN + 1) * WPAD + r % WIN + 1] = inb[i];
        }
    }
    __syncthreads();

    int w0 = (threadIdx.x % WTHR) * WV;
    int h  = threadIdx.x / WTHR;
    int oo = threadIdx.y * OV;
    int p  = 0;

    for (int k = 0; k < NT; k++) {
        int t = t0 + k;
        float stg[NSTG];
        if (k + 1 < NT) {
            const float* nb = in + (size_t)(t + 1) * Min + (size_t)n * CHW;
            #pragma unroll
            for (int j = 0; j < NSTG; j++) {
                int idx = tid + j * THR;
                stg[j] = (idx < CHW) ? __ldg(&nb[idx]) : 0.f;
            }
        }
        const float* sb = s_in + p * TILE;
        float acc[OV][WV];
        #pragma unroll
        for (int o = 0; o < OV; o++)
            #pragma unroll
            for (int v = 0; v < WV; v++) acc[o][v] = 0.f;

        #pragma unroll 2
        for (int c = 0; c < CIN; c++) {
            #pragma unroll
            for (int kh = 0; kh < K; kh++) {
                float win[WLEN];
                const float* bp = &sb[(c * HP + h + kh) * WPAD + w0];
                if constexpr (WLEN == 8) {
                    float4 a = *reinterpret_cast<const float4*>(bp);
                    float4 b = *reinterpret_cast<const float4*>(bp + 4);
                    win[0] = a.x; win[1] = a.y; win[2] = a.z; win[3] = a.w;
                    win[4] = b.x; win[5] = b.y; win[6] = b.z; win[7] = b.w;
                } else {
                    float4 a = *reinterpret_cast<const float4*>(bp);
                    float2 b = *reinterpret_cast<const float2*>(bp + 4);
                    win[0] = a.x; win[1] = a.y; win[2] = a.z; win[3] = a.w;
                    win[4] = b.x; win[5] = b.y;
                }
                #pragma unroll
                for (int o = 0; o < OV; o++) {
                    const float* wp = &s_w[((oo + o) * CIN * K + c * K + kh) * KP];
                    float wr[K];
                    if constexpr (K == 5) {
                        float4 a = *reinterpret_cast<const float4*>(wp);
                        wr[0] = a.x; wr[1] = a.y; wr[2] = a.z; wr[3] = a.w; wr[4] = wp[4];
                    } else {
                        float4 a = *reinterpret_cast<const float4*>(wp);
                        wr[0] = a.x; wr[1] = a.y; wr[2] = a.z;
                    }
                    #pragma unroll
                    for (int kw = 0; kw < K; kw++)
                        #pragma unroll
                        for (int v = 0; v < WV; v++)
                            acc[o][v] = fmaf(wr[kw], win[kw + v], acc[o][v]);
                }
            }
        }
        size_t ob = (size_t)t * Mout + (((size_t)n * COUT + o0 + oo) * HOUT + h) * WOUT + w0;
        #pragma unroll
        for (int o = 0; o < OV; o++)
            #pragma unroll
            for (int v = 0; v < WV; v++)
                out[ob + (size_t)o * (HOUT * WOUT) + v] = acc[o][v];

        if (k + 1 < NT) {
            float* db = s_in + (p ^ 1) * TILE;
            #pragma unroll
            for (int j = 0; j < NSTG; j++) {
                int idx = tid + j * THR;
                if (idx < CHW) {
                    int c = idx / (HIN * WIN), r = idx % (HIN * WIN);
                    db[(c * HP + r / WIN + 1) * WPAD + r % WIN + 1] = stg[j];
                }
            }
        }
        __syncthreads();
        p ^= 1;
    }
}

// ---------------- static conv (conv2/conv3): TT timesteps per block ----------------
template<int CIN, int K, int HIN, int WIN, int HOUT, int WOUT,
         int COUT, int OBLK, int OV, int WV, int TT>
__global__ void conv_p(const float* __restrict__ in, const float* __restrict__ wgt,
                       float* __restrict__ out, int Min, int Mout) {
    constexpr int HP    = HIN + 2;
    constexpr int WPAD  = (WIN + 2 + 3) & ~3;
    constexpr int KP    = (K + 3) & ~3;
    constexpr int TILE  = CIN * HP * WPAD;
    constexpr int WLEN  = WV + K - 1;
    constexpr int WTHR  = WOUT / WV;
    constexpr int CKK   = CIN * K * K;
    extern __shared__ float smem[];
    float* s_in = smem;
    float* s_w  = smem + TT * TILE;

    int t0 = blockIdx.z * TT, n = blockIdx.y, o0 = blockIdx.x * OBLK;
    int nth = blockDim.x * blockDim.y;
    int tid = threadIdx.y * blockDim.x + threadIdx.x;

    for (int i = tid; i < TT * TILE; i += nth) s_in[i] = 0.f;
    __syncthreads();
    #pragma unroll
    for (int tt = 0; tt < TT; tt++) {
        const float* inb = in + (size_t)(t0 + tt) * Min + (size_t)n * CIN * HIN * WIN;
        for (int i = tid; i < CIN * HIN * WIN; i += nth) {
            int c = i / (HIN * WIN), r = i % (HIN * WIN);
            s_in[tt * TILE + (c * HP + r / WIN + 1) * WPAD + r % WIN + 1] = inb[i];
        }
    }
    for (int i = tid; i < OBLK * CKK; i += nth) {
        int o = i / CKK, r = i % CKK;
        s_w[(o * CIN * K + r / K) * KP + r % K] = wgt[(size_t)(o0 + o) * CKK + r];
    }
    __syncthreads();

    int w0 = (threadIdx.x % WTHR) * WV;
    int h  = threadIdx.x / WTHR;
    int oo = threadIdx.y * OV;

    float acc[TT][OV][WV];
    #pragma unroll
    for (int tt = 0; tt < TT; tt++)
        #pragma unroll
        for (int o = 0; o < OV; o++)
            #pragma unroll
            for (int v = 0; v < WV; v++) acc[tt][o][v] = 0.f;

    #pragma unroll 2
    for (int c = 0; c < CIN; c++) {
        #pragma unroll
        for (int kh = 0; kh < K; kh++) {
            float win[TT][WLEN];
            #pragma unroll
            for (int tt = 0; tt < TT; tt++) {
                const float* bp = &s_in[tt * TILE + (c * HP + h + kh) * WPAD + w0];
                float4 a = *reinterpret_cast<const float4*>(bp);
                float2 b = *reinterpret_cast<const float2*>(bp + 4);
                win[tt][0] = a.x; win[tt][1] = a.y; win[tt][2] = a.z; win[tt][3] = a.w;
                win[tt][4] = b.x; win[tt][5] = b.y;
            }
            #pragma unroll
            for (int o = 0; o < OV; o++) {
                const float* wp = &s_w[((oo + o) * CIN * K + c * K + kh) * KP];
                float4 a = *reinterpret_cast<const float4*>(wp);
                float wr[3] = {a.x, a.y, a.z};
                #pragma unroll
                for (int kw = 0; kw < K; kw++)
                    #pragma unroll
                    for (int tt = 0; tt < TT; tt++)
                        #pragma unroll
                        for (int v = 0; v < WV; v++)
                            acc[tt][o][v] = fmaf(wr[kw], win[tt][kw + v], acc[tt][o][v]);
            }
        }
    }
    #pragma unroll
    for (int tt = 0; tt < TT; tt++) {
        size_t ob = (size_t)(t0 + tt) * Mout
                  + (((size_t)n * COUT + o0 + oo) * HOUT + h) * WOUT + w0;
        #pragma unroll
        for (int o = 0; o < OV; o++)
            #pragma unroll
            for (int v = 0; v < WV; v++)
                out[ob + (size_t)o * (HOUT * WOUT) + v] = acc[tt][o][v];
    }
}

// ---------------- final spike scan -> T-minor d_out ----------------
__global__ void spike_lut_out(const float* __restrict__ u, float* __restrict__ out, int M) {
    __shared__ float lut[1024];
    build_rlut(lut);
    __syncthreads();
    int m = blockIdx.x * blockDim.x + threadIdx.x;
    if (m >= M) return;
    unsigned mask = 0;
    float cur[4], nxt[4];
    #pragma unroll
    for (int j = 0; j < 4; j++) cur[j] = u[(size_t)j * M + m];
    for (int tb = 0; tb < T; tb += 4) {
        if (tb + 4 < T) {
            #pragma unroll
            for (int j = 0; j < 4; j++) nxt[j] = __ldg(&u[(size_t)(tb + 4 + j) * M + m]);
        }
        #pragma unroll
        for (int j = 0; j < 4; j++) {
            int t = tb + j;
            float ueff = cur[j] + lut[mask];
            bool b = ueff >= 10.f;
            out[(size_t)m * T + t] = b ? 1.f : 0.f;
            mask = ((mask << 1) | (unsigned)b) & 1023u;
        }
        #pragma unroll
        for (int j = 0; j < 4; j++) cur[j] = nxt[j];
    }
}

// ---------------- dense on s5: double-buffered smem, warp per output ----------------
__global__ void dense_w(const float* __restrict__ in, const float* __restrict__ wfc,
                        float* __restrict__ out) {
    __shared__ float s_in[2][4096];
    int n = blockIdx.x, tg = blockIdx.y;
    int tid = threadIdx.x;                 // 320
    int o = tid >> 5, lane = tid & 31;
    const float* pw = wfc + o * 4096;
    {
        const float* pin = in + (size_t)(tg * 10) * 32768 + n * 4096;
        for (int i = tid; i < 4096; i += 320) s_in[0][i] = pin[i];
    }
    __syncthreads();
    for (int k = 0; k < 10; k++) {
        int t = tg * 10 + k;
        if (k + 1 < 10) {
            const float* pin = in + (size_t)(t + 1) * 32768 + n * 4096;
            for (int i = tid; i < 4096; i += 320) s_in[(k + 1) & 1][i] = __ldg(&pin[i]);
        }
        const float* sb = s_in[k & 1];
        float acc = 0.f;
        #pragma unroll 4
        for (int i = lane; i < 4096; i += 32) acc = fmaf(pw[i], sb[i], acc);
        #pragma unroll
        for (int off = 16; off; off >>= 1) acc += __shfl_down_sync(0xffffffffu, acc, off);
        if (lane == 0) out[(size_t)t * 80 + n * 10 + o] = acc;
        __syncthreads();
    }
}

// ---------------- launch ----------------
extern "C" void kernel_launch(void* const* d_in, const int* in_sizes, int n_in,
                              void* d_out, int out_size) {
    const float* x   = (const float*)d_in[0];
    const float* w1  = (const float*)d_in[1];
    const float* w2  = (const float*)d_in[2];
    const float* w3  = (const float*)d_in[3];
    const float* wfc = (const float*)d_in[4];
    float* out = (float*)d_out;

    void *pY, *pX, *pZ, *pB;
    cudaGetSymbolAddress(&pY, g_bufY);
    cudaGetSymbolAddress(&pX, g_bufX);
    cudaGetSymbolAddress(&pZ, g_bufZ);
    cudaGetSymbolAddress(&pB, g_bits);
    float* Y = (float*)pY;
    float* X = (float*)pX;
    float* Z = (float*)pZ;
    unsigned* B  = (unsigned*)pB;
    unsigned* CB = B + 327680;

    // round-12 proven conv configuration
    auto c1 = conv_db<2, 5, 34, 34, 32, 32, 16, 4, 4, 4, 5, 256>;
    auto c2 = conv_p<16, 3, 16, 16, 16, 16, 32, 32, 4, 4, 2>;
    auto c3 = conv_p<32, 3, 8, 8, 8, 8, 64, 32, 2, 4, 4>;
    const int s1b = (2 * 2 * 36 * 36 + 4 * 2 * 5 * 8) * 4;      // ~22 KB
    const int s2b = (2 * 16 * 18 * 20 + 32 * 16 * 3 * 4) * 4;   // ~70.7 KB
    const int s3b = (4 * 32 * 10 * 12 + 32 * 32 * 3 * 4) * 4;   // ~110.6 KB
    cudaFuncSetAttribute(c2, cudaFuncAttributeMaxDynamicSharedMemorySize, s2b);
    cudaFuncSetAttribute(c3, cudaFuncAttributeMaxDynamicSharedMemorySize, s3b);

    init_filters<<<1, 128>>>();

    // ---- layer 1: psp(x) -> conv1 -> spikepool (count bitplanes) ----
    pack_bits_rm<<<(18496 * NW + 255) / 256, 256>>>(x, B, 18496);
    psp_frombits<<<dim3(73, T / JT), 256>>>(B, X, 18496);
    c1<<<dim3(4, 8, T / 5), dim3(256, 1), s1b>>>(X, w1, Y, 18496, 131072);
    spikepool_bits<32, 32><<<128, 256>>>(Y, CB, 32768);

    // ---- layer 2 tail + layer 3 ----
    spikecnt_bits<<<128, 256>>>(CB, B, 32768);
    psp_frombits<<<dim3(128, T / JT), 256>>>(B, X, 32768);
    c2<<<dim3(1, 8, T / 2), dim3(64, 8), s2b>>>(X, w2, Y, 32768, 65536);
    spikepool_bits<16, 16><<<64, 256>>>(Y, CB, 16384);

    // ---- layer 4 tail + layer 5 ----
    spikecnt_bits<<<64, 256>>>(CB, B, 16384);
    psp_frombits<<<dim3(64, T / JT), 256>>>(B, X, 16384);
    c3<<<dim3(2, 8, T / 4), dim3(16, 16), s3b>>>(X, w3, Y, 16384, 32768);

    // ---- output (commuted): s5 float -> dense(s5) -> psp (tiny) -> spike ----
    spike_f<<<128, 256>>>(Y, X, 32768);
    dense_w<<<dim3(8, T / 10), 320>>>(X, wfc, Z);
    psp_t<<<dim3(1, T / JT), 256>>>(Z, Z + 1048576, 80);
    spike_lut_out<<<1, 128>>>(Z + 1048576, out, 80);
}